// round 7
// baseline (speedup 1.0000x reference)
#include <cuda_runtime.h>
#include <cuda_bf16.h>

// StixelLoss v7: TMA bulk (UBLKCP) staged pipeline, thread-per-column scan.
// inputs:  (B=256, C=2, H=192, W=256) f32 in (1e-4, 1-1e-4)
// targets: (1, B, C, H, W) f32
// out:     scalar f32 = 1.0*bce_mean + 0.001*cuts + 0.1*dense

#define HH   192
#define WW   256
#define NBC  512
#define RPS  4            // rows per stage
#define NST  5            // pipeline stages
#define NIT  (HH / RPS)   // 48 iterations
#define STAGE_BYTES (RPS * WW * 4)   // 4096 per tensor

__global__ void sx_zero_kernel(float* out) {
    if (threadIdx.x == 0) out[0] = 0.0f;
}

__device__ __forceinline__ unsigned sm32(const void* p) {
    return (unsigned)__cvta_generic_to_shared(p);
}

__device__ __forceinline__ void bulk_in(unsigned dst, const float* src, unsigned mbar) {
    asm volatile(
        "cp.async.bulk.shared::cluster.global.mbarrier::complete_tx::bytes "
        "[%0], [%1], %2, [%3];"
        :: "r"(dst), "l"(src), "r"((unsigned)STAGE_BYTES), "r"(mbar) : "memory");
}

__device__ __forceinline__ void wait_parity(unsigned mbar, unsigned ph) {
    asm volatile(
        "{\n\t"
        ".reg .pred P;\n\t"
        "WL_%=:\n\t"
        "mbarrier.try_wait.parity.acquire.cta.shared::cta.b64 P, [%0], %1, 0x989680;\n\t"
        "@P bra.uni WD_%=;\n\t"
        "bra.uni WL_%=;\n\t"
        "WD_%=:\n\t"
        "}"
        :: "r"(mbar), "r"(ph) : "memory");
}

__global__ __launch_bounds__(256)
void stixel_kernel(const float* __restrict__ inp,
                   const float* __restrict__ tgt,
                   float* __restrict__ out) {
    __shared__ __align__(16) float sp [NST][RPS][WW];   // staged inputs
    __shared__ __align__(16) float stg[NST][RPS][WW];   // staged targets
    __shared__ __align__(8)  unsigned long long mb_full[NST];
    __shared__ float sred[8];

    const int bc  = blockIdx.x;      // b*2 + c
    const int c   = bc & 1;
    const int col = threadIdx.x;     // 0..255 = column

    const float* gp = inp + (size_t)bc * (HH * WW);
    const float* gt = tgt + (size_t)bc * (HH * WW);

    if (threadIdx.x == 0) {
        #pragma unroll
        for (int s = 0; s < NST; ++s)
            asm volatile("mbarrier.init.shared.b64 [%0], 1;"
                         :: "r"(sm32(&mb_full[s])) : "memory");
    }
    __syncthreads();

    // prologue: fill stages 0..NST-2 (iterations 0..3)
    if (threadIdx.x == 0) {
        #pragma unroll
        for (int j = 0; j < NST - 1; ++j) {
            unsigned mb = sm32(&mb_full[j]);
            asm volatile("mbarrier.arrive.expect_tx.shared.b64 _, [%0], %1;"
                         :: "r"(mb), "r"(2u * STAGE_BYTES) : "memory");
            bulk_in(sm32(&sp [j][0][0]), gp + j * (RPS * WW), mb);
            bulk_in(sm32(&stg[j][0][0]), gt + j * (RPS * WW), mb);
        }
    }

    float bce   = 0.0f;
    float dense = 0.0f;
    int   cuts  = 0;
    int   prev  = -1;          // -1 = no visible predecessor
    int   cs = 0, cph = 0;     // consumer stage / phase parity
    int   ps = NST - 1;        // producer stage
    int   pit = NST - 1;       // next fill iteration

    for (int w = 0; w < 6; ++w) {          // 6 mask words x 32 rows
        unsigned curw = 0;
        #pragma unroll
        for (int k = 0; k < 8; ++k) {      // 8 stages (4 rows each) per word
            // stage `ps` was consumed at the previous iteration; this barrier
            // makes that consumption visible before refilling it.
            __syncthreads();
            if (threadIdx.x == 0 && pit < NIT) {
                unsigned mb = sm32(&mb_full[ps]);
                asm volatile("mbarrier.arrive.expect_tx.shared.b64 _, [%0], %1;"
                             :: "r"(mb), "r"(2u * STAGE_BYTES) : "memory");
                bulk_in(sm32(&sp [ps][0][0]), gp + pit * (RPS * WW), mb);
                bulk_in(sm32(&stg[ps][0][0]), gt + pit * (RPS * WW), mb);
            }
            ++pit;
            if (++ps == NST) ps = 0;

            // wait for current stage, then consume 4 rows
            wait_parity(sm32(&mb_full[cs]), (unsigned)cph);
            #pragma unroll
            for (int i = 0; i < RPS; ++i) {
                float p = sp [cs][i][col];
                float t = stg[cs][i][col];
                float lp  = __log2f(p);
                float l1p = __log2f(1.0f - p);
                bce += l1p + t * (lp - l1p);
                if (p > 0.5f) curw |= (1u << (k * RPS + i));
            }
            if (++cs == NST) { cs = 0; cph ^= 1; }
        }

        if (c == 0) {
            cuts += __popc(curw);          // all 192 rows of channel 0 count
        } else {
            // dense scan. Reference semantics:
            //  - hit at h=0 invisible (prev!=0 gate)  -> clear bit 0
            //  - h=191 excluded (loop runs h<H-1)     -> clear bit 31 of word 5
            unsigned wb = curw;
            if (w == 0) wb &= ~1u;
            if (w == 5) wb &= 0x7fffffffu;
            const int base = w * 32;
            while (wb) {
                int b = __ffs(wb) - 1;
                wb &= (wb - 1);
                int pos = base + b;
                if (prev >= 0) {
                    float d = (float)(pos - prev);
                    dense += __fdividef(1.0f, d * d * d);
                }
                prev = pos;
            }
        }
    }

    // combine (ALPHA=1, BETA=0.001, GAMMA=0.1); bce is in log2 units
    const float SCALE_BCE = -0.69314718055994531f /
                            (float)((size_t)NBC * HH * WW);
    float val = bce * SCALE_BCE + 0.001f * (float)cuts + 0.1f * dense;

    // block reduction over 256 threads
    #pragma unroll
    for (int off = 16; off > 0; off >>= 1)
        val += __shfl_down_sync(0xffffffffu, val, off);
    int lane = threadIdx.x & 31;
    int wid  = threadIdx.x >> 5;
    if (lane == 0) sred[wid] = val;
    __syncthreads();
    if (wid == 0) {
        val = (lane < 8) ? sred[lane] : 0.0f;
        #pragma unroll
        for (int off = 4; off > 0; off >>= 1)
            val += __shfl_down_sync(0xffffffffu, val, off);
        if (lane == 0) atomicAdd(out, val);
    }
}

extern "C" void kernel_launch(void* const* d_in, const int* in_sizes, int n_in,
                              void* d_out, int out_size) {
    const float* inp = (const float*)d_in[0];
    const float* tgt = (const float*)d_in[1];
    float* out = (float*)d_out;

    sx_zero_kernel<<<1, 32>>>(out);
    stixel_kernel<<<NBC, 256>>>(inp, tgt, out);
}